// round 3
// baseline (speedup 1.0000x reference)
#include <cuda_runtime.h>
#include <math.h>

#define BATCH 4
#define SEQ 2048
#define DMODEL 1024
#define DHEAD 64
#define NT 32            // SEQ / 64 tiles
#define SCALE 0.125f     // DH^-0.5

// Scratch (allowed: __device__ globals, allocated at module load)
__device__ float g_proj[6][BATCH*SEQ*DHEAD];   // 0:Qu 1:Ku 2:Vu 3:Qc 4:Kc 5:Vc
__device__ float g_term1[BATCH][SEQ*SEQ];
__device__ float g_sig[BATCH][SEQ*SEQ];
__device__ float g_Su[BATCH][SEQ*SEQ];
__device__ float g_Sc[BATCH][SEQ*SEQ];

struct WPtrs { const float* w[6]; };

// ---------------------------------------------------------------------------
// Kernel 1: projections. out[row][n] = sum_d x[row][d] * w[d][n]
// Tile: 64 rows x 64 cols (DH), BK=16. 256 threads, 4x4 micro-tile.
// ---------------------------------------------------------------------------
__global__ __launch_bounds__(256) void proj_kernel(const float* __restrict__ x, WPtrs wp) {
    __shared__ float As[16][64];   // [k][m] transposed
    __shared__ float Bs[16][64];   // [k][n]
    const float* __restrict__ w = wp.w[blockIdx.y];
    float* __restrict__ out = g_proj[blockIdx.y];
    const int tid = threadIdx.x;
    const int row0 = blockIdx.x * 64;
    const int tx = tid & 15, ty = tid >> 4;
    const int m0 = ty * 4, n0 = tx * 4;
    const int ar = tid >> 2, acg = tid & 3;     // A tile: 64 rows x 4 float4
    const int br = tid >> 4, bcg = tid & 15;    // B tile: 16 rows x 16 float4
    float acc[4][4] = {};
    for (int k0 = 0; k0 < DMODEL; k0 += 16) {
        float4 av = *(const float4*)&x[(row0 + ar) * DMODEL + k0 + acg * 4];
        float4 bv = *(const float4*)&w[(k0 + br) * DHEAD + bcg * 4];
        As[acg*4+0][ar] = av.x; As[acg*4+1][ar] = av.y;
        As[acg*4+2][ar] = av.z; As[acg*4+3][ar] = av.w;
        *(float4*)&Bs[br][bcg*4] = bv;
        __syncthreads();
        #pragma unroll
        for (int kk = 0; kk < 16; kk++) {
            float a[4], b[4];
            *(float4*)a = *(const float4*)&As[kk][m0];
            *(float4*)b = *(const float4*)&Bs[kk][n0];
            #pragma unroll
            for (int i = 0; i < 4; i++)
                #pragma unroll
                for (int j = 0; j < 4; j++) acc[i][j] += a[i] * b[j];
        }
        __syncthreads();
    }
    #pragma unroll
    for (int i = 0; i < 4; i++) {
        float4 o = make_float4(acc[i][0], acc[i][1], acc[i][2], acc[i][3]);
        *(float4*)&out[(row0 + m0 + i) * DHEAD + n0] = o;
    }
}

// ---------------------------------------------------------------------------
// Kernel 2a: term1[i][j] = causal * scale * <Qc[i], Vu[j]>
//            S_c[i][j]   = causal ? scale * <Qc[i], Kc[j]> : -inf
// Only lower-triangular tiles (tj <= ti).
// ---------------------------------------------------------------------------
__global__ __launch_bounds__(256) void term1_sc_kernel() {
    const int ti = blockIdx.x, tj = blockIdx.y, b = blockIdx.z;
    if (tj > ti) return;
    __shared__ float Qs[64][64];   // [d][i]
    __shared__ float Vs[64][64];   // [d][j]
    __shared__ float Ks[64][64];   // [d][j]
    const float* __restrict__ Qc = g_proj[3] + b * SEQ * DHEAD;
    const float* __restrict__ Vu = g_proj[2] + b * SEQ * DHEAD;
    const float* __restrict__ Kc = g_proj[4] + b * SEQ * DHEAD;
    const int tid = threadIdx.x;
    const int i0 = ti * 64, j0 = tj * 64;
    #pragma unroll
    for (int l = 0; l < 4; l++) {
        int idx = tid + l * 256;
        int r = idx >> 4, cg = idx & 15;
        float4 q = *(const float4*)&Qc[(i0 + r) * DHEAD + cg * 4];
        float4 v = *(const float4*)&Vu[(j0 + r) * DHEAD + cg * 4];
        float4 k = *(const float4*)&Kc[(j0 + r) * DHEAD + cg * 4];
        Qs[cg*4+0][r] = q.x; Qs[cg*4+1][r] = q.y; Qs[cg*4+2][r] = q.z; Qs[cg*4+3][r] = q.w;
        Vs[cg*4+0][r] = v.x; Vs[cg*4+1][r] = v.y; Vs[cg*4+2][r] = v.z; Vs[cg*4+3][r] = v.w;
        Ks[cg*4+0][r] = k.x; Ks[cg*4+1][r] = k.y; Ks[cg*4+2][r] = k.z; Ks[cg*4+3][r] = k.w;
    }
    __syncthreads();
    const int tx = tid & 15, ty = tid >> 4;
    const int m0 = ty * 4, n0 = tx * 4;
    float acc1[4][4] = {}, acc2[4][4] = {};
    #pragma unroll 8
    for (int d = 0; d < 64; d++) {
        float a[4], bv[4], bk[4];
        *(float4*)a  = *(const float4*)&Qs[d][m0];
        *(float4*)bv = *(const float4*)&Vs[d][n0];
        *(float4*)bk = *(const float4*)&Ks[d][n0];
        #pragma unroll
        for (int i = 0; i < 4; i++)
            #pragma unroll
            for (int j = 0; j < 4; j++) {
                acc1[i][j] += a[i] * bv[j];
                acc2[i][j] += a[i] * bk[j];
            }
    }
    float* __restrict__ t1 = g_term1[b];
    float* __restrict__ sc = g_Sc[b];
    #pragma unroll
    for (int i = 0; i < 4; i++) {
        int gi = i0 + m0 + i;
        float o1[4], o2[4];
        #pragma unroll
        for (int j = 0; j < 4; j++) {
            int gj = j0 + n0 + j;
            bool c = (gj <= gi);
            o1[j] = c ? acc1[i][j] * SCALE : 0.0f;
            o2[j] = c ? acc2[i][j] * SCALE : -INFINITY;
        }
        *(float4*)&t1[gi * SEQ + j0 + n0] = *(float4*)o1;
        *(float4*)&sc[gi * SEQ + j0 + n0] = *(float4*)o2;
    }
}

// ---------------------------------------------------------------------------
// Kernel 2b: sig[k][j] = (j > k) ? sigmoid(scale * <Qu[k], Ku[j]>) : 0
// Only upper-triangular tiles (tj >= tk).
// ---------------------------------------------------------------------------
__global__ __launch_bounds__(256) void sig_kernel() {
    const int tk = blockIdx.x, tj = blockIdx.y, b = blockIdx.z;
    if (tj < tk) return;
    __shared__ float Qs[64][64];   // [d][k]
    __shared__ float Ks[64][64];   // [d][j]
    const float* __restrict__ Qu = g_proj[0] + b * SEQ * DHEAD;
    const float* __restrict__ Ku = g_proj[1] + b * SEQ * DHEAD;
    const int tid = threadIdx.x;
    const int k0 = tk * 64, j0 = tj * 64;
    #pragma unroll
    for (int l = 0; l < 4; l++) {
        int idx = tid + l * 256;
        int r = idx >> 4, cg = idx & 15;
        float4 q = *(const float4*)&Qu[(k0 + r) * DHEAD + cg * 4];
        float4 k = *(const float4*)&Ku[(j0 + r) * DHEAD + cg * 4];
        Qs[cg*4+0][r] = q.x; Qs[cg*4+1][r] = q.y; Qs[cg*4+2][r] = q.z; Qs[cg*4+3][r] = q.w;
        Ks[cg*4+0][r] = k.x; Ks[cg*4+1][r] = k.y; Ks[cg*4+2][r] = k.z; Ks[cg*4+3][r] = k.w;
    }
    __syncthreads();
    const int tx = tid & 15, ty = tid >> 4;
    const int m0 = ty * 4, n0 = tx * 4;
    float acc[4][4] = {};
    #pragma unroll 8
    for (int d = 0; d < 64; d++) {
        float a[4], bb[4];
        *(float4*)a  = *(const float4*)&Qs[d][m0];
        *(float4*)bb = *(const float4*)&Ks[d][n0];
        #pragma unroll
        for (int i = 0; i < 4; i++)
            #pragma unroll
            for (int j = 0; j < 4; j++) acc[i][j] += a[i] * bb[j];
    }
    float* __restrict__ sg = g_sig[b];
    #pragma unroll
    for (int i = 0; i < 4; i++) {
        int gk = k0 + m0 + i;
        float o[4];
        #pragma unroll
        for (int j = 0; j < 4; j++) {
            int gj = j0 + n0 + j;
            o[j] = (gj > gk) ? 1.0f / (1.0f + __expf(-acc[i][j] * SCALE)) : 0.0f;
        }
        *(float4*)&sg[gk * SEQ + j0 + n0] = *(float4*)o;
    }
}

// ---------------------------------------------------------------------------
// Kernel 3: S_u[i][k] = sum_j term1[i][j] * sig[k][j]
// Nonzero only for k < i; only tiles tk <= ti, j-tiles tk..ti contribute.
// ---------------------------------------------------------------------------
__global__ __launch_bounds__(256) void su_kernel() {
    const int ti = blockIdx.x, tk = blockIdx.y, b = blockIdx.z;
    if (tk > ti) return;
    __shared__ float Ts[64][64];   // [j][i]
    __shared__ float Gs[64][64];   // [j][k]
    const float* __restrict__ t1 = g_term1[b];
    const float* __restrict__ sg = g_sig[b];
    const int tid = threadIdx.x;
    const int i0 = ti * 64, k0 = tk * 64;
    const int tx = tid & 15, ty = tid >> 4;
    const int m0 = ty * 4, n0 = tx * 4;
    float acc[4][4] = {};
    for (int tj = tk; tj <= ti; tj++) {
        int j0 = tj * 64;
        #pragma unroll
        for (int l = 0; l < 4; l++) {
            int idx = tid + l * 256;
            int r = idx >> 4, cg = idx & 15;
            float4 a = *(const float4*)&t1[(i0 + r) * SEQ + j0 + cg * 4];
            float4 g = *(const float4*)&sg[(k0 + r) * SEQ + j0 + cg * 4];
            Ts[cg*4+0][r] = a.x; Ts[cg*4+1][r] = a.y; Ts[cg*4+2][r] = a.z; Ts[cg*4+3][r] = a.w;
            Gs[cg*4+0][r] = g.x; Gs[cg*4+1][r] = g.y; Gs[cg*4+2][r] = g.z; Gs[cg*4+3][r] = g.w;
        }
        __syncthreads();
        #pragma unroll 8
        for (int j = 0; j < 64; j++) {
            float a[4], bb[4];
            *(float4*)a  = *(const float4*)&Ts[j][m0];
            *(float4*)bb = *(const float4*)&Gs[j][n0];
            #pragma unroll
            for (int i = 0; i < 4; i++)
                #pragma unroll
                for (int jj = 0; jj < 4; jj++) acc[i][jj] += a[i] * bb[jj];
        }
        __syncthreads();
    }
    float* __restrict__ su = g_Su[b];
    #pragma unroll
    for (int i = 0; i < 4; i++) {
        float4 o = make_float4(acc[i][0], acc[i][1], acc[i][2], acc[i][3]);
        *(float4*)&su[(i0 + m0 + i) * SEQ + k0 + n0] = o;
    }
}

// ---------------------------------------------------------------------------
// Kernel 4: fused online softmax + attn @ V_c.
// One block per (b, 64-row i-tile). logits[i][j] = S_c - silu(S_u), j <= i.
// Thread layout: r = tid/4 (row), q = tid%4 (16-wide d/col slice).
// ---------------------------------------------------------------------------
__global__ __launch_bounds__(256) void softmax_av_kernel(float* __restrict__ out) {
    const int ti = blockIdx.x, b = blockIdx.y;
    __shared__ float Ls[64][65];   // logits, then p
    __shared__ float Vs[64][64];   // V_c tile [j][d]
    const float* __restrict__ sc = g_Sc[b];
    const float* __restrict__ su = g_Su[b];
    const float* __restrict__ Vc = g_proj[5] + b * SEQ * DHEAD;
    const int tid = threadIdx.x;
    const int i0 = ti * 64;
    const int r = tid >> 2, q = tid & 3, d0 = q * 16;
    float m_prev = -INFINITY, Z = 0.0f;
    float acc[16] = {};
    for (int tj = 0; tj <= ti; tj++) {
        const int j0 = tj * 64;
        __syncthreads();   // prior accumulation done before tile reuse
        #pragma unroll
        for (int l = 0; l < 4; l++) {
            int idx = tid + l * 256;
            int rr = idx >> 4, cg = idx & 15;
            *(float4*)&Vs[rr][cg*4] = *(const float4*)&Vc[(j0 + rr) * DHEAD + cg * 4];
        }
        #pragma unroll
        for (int l = 0; l < 16; l++) {
            int idx = tid + l * 256;
            int rr = idx >> 6, cc = idx & 63;
            int gi = i0 + rr, gj = j0 + cc;
            float lv;
            if (gj > gi) {
                lv = -INFINITY;
            } else {
                float s = su[gi * SEQ + gj];
                float sil = s / (1.0f + __expf(-s));
                lv = sc[gi * SEQ + gj] - sil;
            }
            Ls[rr][cc] = lv;
        }
        __syncthreads();
        // row max over this tile (4 lanes per row)
        float mt = -INFINITY;
        #pragma unroll
        for (int c = 0; c < 16; c++) mt = fmaxf(mt, Ls[r][d0 + c]);
        mt = fmaxf(mt, __shfl_xor_sync(0xffffffffu, mt, 1));
        mt = fmaxf(mt, __shfl_xor_sync(0xffffffffu, mt, 2));
        float m_new = fmaxf(m_prev, mt);
        float scl = __expf(m_prev - m_new);   // tile 0: exp(-inf)=0; m_new always finite
        float zl = 0.0f;
        #pragma unroll
        for (int c = 0; c < 16; c++) {
            float p = __expf(Ls[r][d0 + c] - m_new);
            Ls[r][d0 + c] = p;
            zl += p;
        }
        zl += __shfl_xor_sync(0xffffffffu, zl, 1);
        zl += __shfl_xor_sync(0xffffffffu, zl, 2);
        Z = Z * scl + zl;
        m_prev = m_new;
        #pragma unroll
        for (int d = 0; d < 16; d++) acc[d] *= scl;
        __syncthreads();   // all p values of the row visible
        #pragma unroll 4
        for (int c = 0; c < 64; c++) {
            float p = Ls[r][c];
            float v[16];
            *(float4*)&v[0]  = *(const float4*)&Vs[c][d0];
            *(float4*)&v[4]  = *(const float4*)&Vs[c][d0 + 4];
            *(float4*)&v[8]  = *(const float4*)&Vs[c][d0 + 8];
            *(float4*)&v[12] = *(const float4*)&Vs[c][d0 + 12];
            #pragma unroll
            for (int d = 0; d < 16; d++) acc[d] += p * v[d];
        }
    }
    const float inv = 1.0f / Z;
    const int gi = i0 + r;
    #pragma unroll
    for (int g4 = 0; g4 < 4; g4++) {
        float4 o = make_float4(acc[g4*4+0]*inv, acc[g4*4+1]*inv,
                               acc[g4*4+2]*inv, acc[g4*4+3]*inv);
        *(float4*)&out[((size_t)(b * SEQ + gi)) * DHEAD + d0 + g4 * 4] = o;
    }
}

// ---------------------------------------------------------------------------
extern "C" void kernel_launch(void* const* d_in, const int* in_sizes, int n_in,
                              void* d_out, int out_size) {
    const float* x = (const float*)d_in[0];
    WPtrs wp;
    for (int i = 0; i < 6; i++) wp.w[i] = (const float*)d_in[1 + i];

    dim3 g1((BATCH * SEQ) / 64, 6);
    proj_kernel<<<g1, 256>>>(x, wp);

    dim3 g2(NT, NT, BATCH);
    term1_sc_kernel<<<g2, 256>>>();
    sig_kernel<<<g2, 256>>>();
    su_kernel<<<g2, 256>>>();

    dim3 g4(NT, BATCH);
    softmax_av_kernel<<<g4, 256>>>((float*)d_out);
}

// round 6
// speedup vs baseline: 1.5077x; 1.5077x over previous
#include <cuda_runtime.h>
#include <math.h>

#define BATCH 4
#define SEQ 2048
#define DMODEL 1024
#define DHEAD 64
#define SCALE 0.125f     // DH^-0.5

// Scratch (__device__ globals — allowed)
__device__ float g_proj[6][BATCH*SEQ*DHEAD];   // 0:Qu 1:Ku 2:Vu 3:Qc 4:Kc 5:Vc
__device__ float g_term1[BATCH][SEQ*SEQ];
__device__ float g_sig[BATCH][SEQ*SEQ];
__device__ float g_Su[BATCH][SEQ*SEQ];
__device__ float g_Sc[BATCH][SEQ*SEQ];

struct WPtrs { const float* w[6]; };

// ---------------------------------------------------------------------------
// Kernel 1: projections. out[row][n] = sum_d x[row][d] * w[d][n]
// Tile 128 rows x 64 cols, BK=16, 128 threads, 8x8 micro-tile.
// ---------------------------------------------------------------------------
__global__ __launch_bounds__(128) void proj_kernel(const float* __restrict__ x, WPtrs wp) {
    __shared__ float As[16][132];   // [k][m] transposed, pad 4
    __shared__ float Bs[16][64];    // [k][n]
    const float* __restrict__ w = wp.w[blockIdx.y];
    float* __restrict__ out = g_proj[blockIdx.y];   // device-side global ref: OK
    const int tid = threadIdx.x;
    const int row0 = blockIdx.x * 128;
    const int tx = tid & 7, ty = tid >> 3;
    const int m0 = ty * 8, n0 = tx * 8;
    float acc[8][8] = {};
    for (int k0 = 0; k0 < DMODEL; k0 += 16) {
        #pragma unroll
        for (int l = 0; l < 4; l++) {                 // A: 128x16 = 512 float4
            int idx = tid + l * 128;
            int r = idx >> 2, cg = idx & 3;
            float4 av = *(const float4*)&x[(row0 + r) * DMODEL + k0 + cg * 4];
            As[cg*4+0][r] = av.x; As[cg*4+1][r] = av.y;
            As[cg*4+2][r] = av.z; As[cg*4+3][r] = av.w;
        }
        #pragma unroll
        for (int l = 0; l < 2; l++) {                 // B: 16x64 = 256 float4
            int idx = tid + l * 128;
            int br = idx >> 4, bc = idx & 15;
            *(float4*)&Bs[br][bc*4] = *(const float4*)&w[(k0 + br) * DHEAD + bc * 4];
        }
        __syncthreads();
        #pragma unroll
        for (int kk = 0; kk < 16; kk++) {
            float a[8], b[8];
            *(float4*)&a[0] = *(const float4*)&As[kk][m0];
            *(float4*)&a[4] = *(const float4*)&As[kk][m0+4];
            *(float4*)&b[0] = *(const float4*)&Bs[kk][n0];
            *(float4*)&b[4] = *(const float4*)&Bs[kk][n0+4];
            #pragma unroll
            for (int i = 0; i < 8; i++)
                #pragma unroll
                for (int j = 0; j < 8; j++) acc[i][j] += a[i] * b[j];
        }
        __syncthreads();
    }
    #pragma unroll
    for (int i = 0; i < 8; i++) {
        float* o = &out[(row0 + m0 + i) * DHEAD + n0];
        *(float4*)&o[0] = make_float4(acc[i][0], acc[i][1], acc[i][2], acc[i][3]);
        *(float4*)&o[4] = make_float4(acc[i][4], acc[i][5], acc[i][6], acc[i][7]);
    }
}

// ---------------------------------------------------------------------------
// Generic DH=64 inner-product kernel, 128x128 tile, 8x8 micro.
// Pointers resolved from device globals INSIDE the kernel (host cannot take
// the address of a __device__ array — that was the round-3 bug).
// OP 0: term1 = (j<=i) ? Qc.Vu^T*scale : 0             (lower tiles)
// OP 1: S_c   = (j<=i) ? Qc.Kc^T*scale : -inf          (lower tiles)
// OP 2: sig   = (j>k)  ? sigmoid(Qu.Ku^T*scale) : 0    (upper tiles)
// ---------------------------------------------------------------------------
template <int OP>
__global__ __launch_bounds__(256) void qk128_kernel() {
    const int tiB = blockIdx.x, tjB = blockIdx.y, b = blockIdx.z;
    if (OP == 2) { if (tjB < tiB) return; } else { if (tjB > tiB) return; }
    const float* __restrict__ Ab =
        (OP == 2 ? g_proj[0] : g_proj[3]) + b * SEQ * DHEAD;
    const float* __restrict__ Bb =
        (OP == 0 ? g_proj[2] : OP == 1 ? g_proj[4] : g_proj[1]) + b * SEQ * DHEAD;
    float* __restrict__ Cb =
        (OP == 0 ? g_term1[b] : OP == 1 ? g_Sc[b] : g_sig[b]);
    __shared__ float As[16][132];
    __shared__ float Bs[16][132];
    const int i0 = tiB * 128, j0 = tjB * 128;
    const int tid = threadIdx.x;
    const int tx = tid & 15, ty = tid >> 4;
    const int m0 = ty * 8, n0 = tx * 8;
    float acc[8][8] = {};
    for (int d0 = 0; d0 < DHEAD; d0 += 16) {
        #pragma unroll
        for (int l = 0; l < 2; l++) {                 // 128x16 = 512 float4 each
            int idx = tid + l * 256;
            int r = idx >> 2, cg = idx & 3;
            float4 av = *(const float4*)&Ab[(i0 + r) * DHEAD + d0 + cg * 4];
            float4 bv = *(const float4*)&Bb[(j0 + r) * DHEAD + d0 + cg * 4];
            As[cg*4+0][r] = av.x; As[cg*4+1][r] = av.y;
            As[cg*4+2][r] = av.z; As[cg*4+3][r] = av.w;
            Bs[cg*4+0][r] = bv.x; Bs[cg*4+1][r] = bv.y;
            Bs[cg*4+2][r] = bv.z; Bs[cg*4+3][r] = bv.w;
        }
        __syncthreads();
        #pragma unroll
        for (int kk = 0; kk < 16; kk++) {
            float a[8], bb[8];
            *(float4*)&a[0]  = *(const float4*)&As[kk][m0];
            *(float4*)&a[4]  = *(const float4*)&As[kk][m0+4];
            *(float4*)&bb[0] = *(const float4*)&Bs[kk][n0];
            *(float4*)&bb[4] = *(const float4*)&Bs[kk][n0+4];
            #pragma unroll
            for (int i = 0; i < 8; i++)
                #pragma unroll
                for (int j = 0; j < 8; j++) acc[i][j] += a[i] * bb[j];
        }
        __syncthreads();
    }
    #pragma unroll
    for (int i = 0; i < 8; i++) {
        const int gi = i0 + m0 + i;
        float o[8];
        #pragma unroll
        for (int j = 0; j < 8; j++) {
            const int gj = j0 + n0 + j;
            const float v = acc[i][j] * SCALE;
            if (OP == 0) o[j] = (gj <= gi) ? v : 0.0f;
            if (OP == 1) o[j] = (gj <= gi) ? v : -INFINITY;
            if (OP == 2) o[j] = (gj > gi) ? 1.0f / (1.0f + __expf(-v)) : 0.0f;
        }
        float* cp = &Cb[(size_t)gi * SEQ + j0 + n0];
        *(float4*)&cp[0] = *(float4*)&o[0];
        *(float4*)&cp[4] = *(float4*)&o[4];
    }
}

// ---------------------------------------------------------------------------
// Kernel 3: S_u[i][k] = sum_j term1[i][j] * sig[k][j]   (NT GEMM over SEQ)
// 128x128 C-tile, 8x8 micro, BK=16. Only tk<=ti blocks; j in [k0, i0+128).
// ---------------------------------------------------------------------------
__global__ __launch_bounds__(256) void su_kernel() {
    const int tiB = blockIdx.x, tkB = blockIdx.y, b = blockIdx.z;
    if (tkB > tiB) return;
    const float* __restrict__ t1 = g_term1[b];
    const float* __restrict__ sg = g_sig[b];
    float* __restrict__ su = g_Su[b];
    __shared__ float Ts[16][132];   // [j][i]
    __shared__ float Gs[16][132];   // [j][k]
    const int i0 = tiB * 128, k0 = tkB * 128;
    const int tid = threadIdx.x;
    const int tx = tid & 15, ty = tid >> 4;
    const int m0 = ty * 8, n0 = tx * 8;
    float acc[8][8] = {};
    for (int j0 = k0; j0 < i0 + 128; j0 += 16) {
        #pragma unroll
        for (int l = 0; l < 2; l++) {
            int idx = tid + l * 256;
            int r = idx >> 2, cg = idx & 3;
            float4 av = *(const float4*)&t1[(size_t)(i0 + r) * SEQ + j0 + cg * 4];
            float4 gv = *(const float4*)&sg[(size_t)(k0 + r) * SEQ + j0 + cg * 4];
            Ts[cg*4+0][r] = av.x; Ts[cg*4+1][r] = av.y;
            Ts[cg*4+2][r] = av.z; Ts[cg*4+3][r] = av.w;
            Gs[cg*4+0][r] = gv.x; Gs[cg*4+1][r] = gv.y;
            Gs[cg*4+2][r] = gv.z; Gs[cg*4+3][r] = gv.w;
        }
        __syncthreads();
        #pragma unroll
        for (int kk = 0; kk < 16; kk++) {
            float a[8], bb[8];
            *(float4*)&a[0]  = *(const float4*)&Ts[kk][m0];
            *(float4*)&a[4]  = *(const float4*)&Ts[kk][m0+4];
            *(float4*)&bb[0] = *(const float4*)&Gs[kk][n0];
            *(float4*)&bb[4] = *(const float4*)&Gs[kk][n0+4];
            #pragma unroll
            for (int i = 0; i < 8; i++)
                #pragma unroll
                for (int j = 0; j < 8; j++) acc[i][j] += a[i] * bb[j];
        }
        __syncthreads();
    }
    #pragma unroll
    for (int i = 0; i < 8; i++) {
        float* op = &su[(size_t)(i0 + m0 + i) * SEQ + k0 + n0];
        *(float4*)&op[0] = make_float4(acc[i][0], acc[i][1], acc[i][2], acc[i][3]);
        *(float4*)&op[4] = make_float4(acc[i][4], acc[i][5], acc[i][6], acc[i][7]);
    }
}

// ---------------------------------------------------------------------------
// Kernel 4: fused online softmax + attn @ V_c.
// One block per (b, 32-row i-tile), 256 threads: r=tid/8 (row), q=tid%8 (8-wide d).
// logits[i][j] = S_c[i][j] - silu(S_u[i][j]), j <= i.
// ---------------------------------------------------------------------------
__global__ __launch_bounds__(256) void softmax_av_kernel(float* __restrict__ out) {
    const int t32 = blockIdx.x, b = blockIdx.y;
    __shared__ float Ls[32][65];
    __shared__ float Vs[64][64];
    const float* __restrict__ sc = g_Sc[b];
    const float* __restrict__ su = g_Su[b];
    const float* __restrict__ Vc = g_proj[5] + b * SEQ * DHEAD;
    const int tid = threadIdx.x;
    const int i0 = t32 * 32;
    const int r = tid >> 3, q = tid & 7, d0 = q * 8;
    const int njt = (t32 >> 1) + 1;     // 64-wide j tiles covering j<=i
    float m_prev = -INFINITY, Z = 0.0f;
    float acc[8] = {};
    for (int tj = 0; tj < njt; tj++) {
        const int j0 = tj * 64;
        __syncthreads();    // previous accumulate done before tile reuse
        #pragma unroll
        for (int l = 0; l < 4; l++) {              // Vs: 64x64 = 1024 float4
            int idx = tid + l * 256;
            int rr = idx >> 4, cg = idx & 15;
            *(float4*)&Vs[rr][cg*4] = *(const float4*)&Vc[(j0 + rr) * DHEAD + cg * 4];
        }
        #pragma unroll
        for (int l = 0; l < 8; l++) {              // Ls logits: 32x64
            int idx = tid + l * 256;
            int rr = idx >> 6, cc = idx & 63;
            int gi = i0 + rr, gj = j0 + cc;
            float lv;
            if (gj > gi) {
                lv = -INFINITY;
            } else {
                float s = su[(size_t)gi * SEQ + gj];
                float sil = s / (1.0f + __expf(-s));
                lv = sc[(size_t)gi * SEQ + gj] - sil;
            }
            Ls[rr][cc] = lv;
        }
        __syncthreads();
        // row max over this tile (8 lanes per row)
        float mt = -INFINITY;
        #pragma unroll
        for (int c = 0; c < 8; c++) mt = fmaxf(mt, Ls[r][d0 + c]);
        mt = fmaxf(mt, __shfl_xor_sync(0xffffffffu, mt, 1));
        mt = fmaxf(mt, __shfl_xor_sync(0xffffffffu, mt, 2));
        mt = fmaxf(mt, __shfl_xor_sync(0xffffffffu, mt, 4));
        float m_new = fmaxf(m_prev, mt);           // finite from tile 0 on
        float scl = __expf(m_prev - m_new);        // tile 0: exp(-inf)=0
        float zl = 0.0f;
        #pragma unroll
        for (int c = 0; c < 8; c++) {
            float p = __expf(Ls[r][d0 + c] - m_new);
            Ls[r][d0 + c] = p;
            zl += p;
        }
        zl += __shfl_xor_sync(0xffffffffu, zl, 1);
        zl += __shfl_xor_sync(0xffffffffu, zl, 2);
        zl += __shfl_xor_sync(0xffffffffu, zl, 4);
        Z = Z * scl + zl;
        m_prev = m_new;
        #pragma unroll
        for (int d = 0; d < 8; d++) acc[d] *= scl;
        __syncwarp();    // row's 8 p-lanes are within this warp
        #pragma unroll 8
        for (int c = 0; c < 64; c++) {
            float p = Ls[r][c];
            float v[8];
            *(float4*)&v[0] = *(const float4*)&Vs[c][d0];
            *(float4*)&v[4] = *(const float4*)&Vs[c][d0 + 4];
            #pragma unroll
            for (int d = 0; d < 8; d++) acc[d] += p * v[d];
        }
    }
    const float inv = 1.0f / Z;
    const int gi = i0 + r;
    float* op = &out[((size_t)(b * SEQ + gi)) * DHEAD + d0];
    *(float4*)&op[0] = make_float4(acc[0]*inv, acc[1]*inv, acc[2]*inv, acc[3]*inv);
    *(float4*)&op[4] = make_float4(acc[4]*inv, acc[5]*inv, acc[6]*inv, acc[7]*inv);
}

// ---------------------------------------------------------------------------
extern "C" void kernel_launch(void* const* d_in, const int* in_sizes, int n_in,
                              void* d_out, int out_size) {
    const float* x = (const float*)d_in[0];
    WPtrs wp;
    for (int i = 0; i < 6; i++) wp.w[i] = (const float*)d_in[1 + i];

    dim3 g1((BATCH * SEQ) / 128, 6);
    proj_kernel<<<g1, 128>>>(x, wp);

    dim3 g2(SEQ / 128, SEQ / 128, BATCH);
    qk128_kernel<0><<<g2, 256>>>();   // term1 = Qc.Vu^T (lower)
    qk128_kernel<1><<<g2, 256>>>();   // S_c   = Qc.Kc^T (lower)
    qk128_kernel<2><<<g2, 256>>>();   // sig   = sigmoid(Qu.Ku^T) (upper)

    su_kernel<<<g2, 256>>>();

    dim3 g4(SEQ / 32, BATCH);
    softmax_av_kernel<<<g4, 256>>>((float*)d_out);
}

// round 8
// speedup vs baseline: 1.5825x; 1.0496x over previous
#include <cuda_runtime.h>
#include <math.h>
#include <stdint.h>

#define BATCH 4
#define SEQ 2048
#define DMODEL 1024
#define DHEAD 64
#define SCALE 0.125f     // DH^-0.5
#define BK 16
#define PITCH 20         // BK + 4: conflict-free fragment access

// Scratch (__device__ globals — allowed)
__device__ float g_proj[6][BATCH*SEQ*DHEAD];   // 0:Qu 1:Ku 2:Vu 3:Qc 4:Kc 5:Vc
__device__ float g_term1[BATCH][SEQ*SEQ];
__device__ float g_sig[BATCH][SEQ*SEQ];
__device__ float g_Su[BATCH][SEQ*SEQ];
__device__ float g_Sc[BATCH][SEQ*SEQ];

struct WPtrs { const float* w[6]; };

// ---------------------------------------------------------------------------
// tf32 helpers
// ---------------------------------------------------------------------------
__device__ __forceinline__ uint32_t f2tf32(float f) {
    uint32_t r;
    asm("cvt.rna.tf32.f32 %0, %1;" : "=r"(r) : "f"(f));
    return r;
}

__device__ __forceinline__ void split_store(uint32_t* hi, uint32_t* lo, float4 v) {
    float f[4] = {v.x, v.y, v.z, v.w};
    #pragma unroll
    for (int i = 0; i < 4; i++) {
        uint32_t h = f2tf32(f[i]);
        hi[i] = h;
        lo[i] = f2tf32(f[i] - __uint_as_float(h));
    }
}

// D += A * B  (m16n8k8, tf32 inputs, fp32 accum)
__device__ __forceinline__ void mma_tf32(float c[4],
                                         uint32_t a0, uint32_t a1, uint32_t a2, uint32_t a3,
                                         uint32_t b0, uint32_t b1) {
    asm volatile(
        "mma.sync.aligned.m16n8k8.row.col.f32.tf32.tf32.f32 "
        "{%0,%1,%2,%3}, {%4,%5,%6,%7}, {%8,%9}, {%0,%1,%2,%3};"
        : "+f"(c[0]), "+f"(c[1]), "+f"(c[2]), "+f"(c[3])
        : "r"(a0), "r"(a1), "r"(a2), "r"(a3), "r"(b0), "r"(b1));
}

// ---------------------------------------------------------------------------
// Kernel 1: projections via 3xTF32 mma. out[row][n] = sum_d x[row][d]*w[d][n]
// Block tile 128(m) x 64(n), 4 warps of 32x64, BK=16, K=1024.
// ---------------------------------------------------------------------------
__global__ __launch_bounds__(128) void proj_mma_kernel(const float* __restrict__ x, WPtrs wp) {
    __shared__ uint32_t Ah[128][PITCH], Al[128][PITCH];
    __shared__ uint32_t Bh[64][PITCH],  Bl[64][PITCH];
    const float* __restrict__ w = wp.w[blockIdx.y];
    float* __restrict__ out = g_proj[blockIdx.y];
    const int tid = threadIdx.x;
    const int warp = tid >> 5, lane = tid & 31;
    const int g = lane >> 2, t = lane & 3;
    const int row0 = blockIdx.x * 128;
    const int wm = warp * 32;
    float acc[2][8][4] = {};
    for (int kc = 0; kc < DMODEL; kc += BK) {
        #pragma unroll
        for (int l = 0; l < 4; l++) {               // A: 128x16 = 512 float4
            int idx = tid + l * 128;
            int r = idx >> 2, c4 = (idx & 3) * 4;
            float4 av = *(const float4*)&x[(size_t)(row0 + r) * DMODEL + kc + c4];
            split_store(&Ah[r][c4], &Al[r][c4], av);
        }
        #pragma unroll
        for (int l = 0; l < 2; l++) {               // B: 16k x 64n, store transposed [n][k]
            int idx = tid + l * 128;
            int kr = idx >> 4, n4 = (idx & 15) * 4;
            float4 wv = *(const float4*)&w[(size_t)(kc + kr) * DHEAD + n4];
            float f[4] = {wv.x, wv.y, wv.z, wv.w};
            #pragma unroll
            for (int i = 0; i < 4; i++) {
                uint32_t h = f2tf32(f[i]);
                Bh[n4 + i][kr] = h;
                Bl[n4 + i][kr] = f2tf32(f[i] - __uint_as_float(h));
            }
        }
        __syncthreads();
        #pragma unroll
        for (int ks = 0; ks < 2; ks++) {
            const int ko = ks * 8;
            uint32_t afh[2][4], afl[2][4];
            #pragma unroll
            for (int mt = 0; mt < 2; mt++) {
                int r0 = wm + mt * 16;
                afh[mt][0] = Ah[r0 + g][ko + t];     afh[mt][1] = Ah[r0 + g + 8][ko + t];
                afh[mt][2] = Ah[r0 + g][ko + t + 4]; afh[mt][3] = Ah[r0 + g + 8][ko + t + 4];
                afl[mt][0] = Al[r0 + g][ko + t];     afl[mt][1] = Al[r0 + g + 8][ko + t];
                afl[mt][2] = Al[r0 + g][ko + t + 4]; afl[mt][3] = Al[r0 + g + 8][ko + t + 4];
            }
            #pragma unroll
            for (int nt = 0; nt < 8; nt++) {
                int c0 = nt * 8;
                uint32_t bh0 = Bh[c0 + g][ko + t], bh1 = Bh[c0 + g][ko + t + 4];
                uint32_t bl0 = Bl[c0 + g][ko + t], bl1 = Bl[c0 + g][ko + t + 4];
                #pragma unroll
                for (int mt = 0; mt < 2; mt++) {
                    mma_tf32(acc[mt][nt], afh[mt][0], afh[mt][1], afh[mt][2], afh[mt][3], bh0, bh1);
                    mma_tf32(acc[mt][nt], afh[mt][0], afh[mt][1], afh[mt][2], afh[mt][3], bl0, bl1);
                    mma_tf32(acc[mt][nt], afl[mt][0], afl[mt][1], afl[mt][2], afl[mt][3], bh0, bh1);
                }
            }
        }
        __syncthreads();
    }
    #pragma unroll
    for (int mt = 0; mt < 2; mt++) {
        const int gi0 = row0 + wm + mt * 16 + g;
        #pragma unroll
        for (int nt = 0; nt < 8; nt++) {
            const int gj = nt * 8 + 2 * t;
            *(float2*)&out[(size_t)gi0 * DHEAD + gj] =
                make_float2(acc[mt][nt][0], acc[mt][nt][1]);
            *(float2*)&out[(size_t)(gi0 + 8) * DHEAD + gj] =
                make_float2(acc[mt][nt][2], acc[mt][nt][3]);
        }
    }
}

// ---------------------------------------------------------------------------
// Unified NT GEMM via 3xTF32 mma: C[i][j] = <Arow i, Brow j>, 128x128 block,
// 4 warps of 64x64.
// OP 0: term1 = (j<=i)? v*scale : 0            A=Qc B=Vu  K=64  (lower)
// OP 1: S_c   = (j<=i)? v*scale : -inf         A=Qc B=Kc  K=64  (lower)
// OP 2: sig   = (j>i)?  sigmoid(v*scale) : 0   A=Qu B=Ku  K=64  (upper)
// OP 3: S_u   = v                              A=term1 B=sig, K=[k0, i0+128)
// ---------------------------------------------------------------------------
template <int OP>
__global__ __launch_bounds__(128) void mma_nt_kernel() {
    const int tiB = blockIdx.x, tjB = blockIdx.y, b = blockIdx.z;
    if (OP == 2) { if (tjB < tiB) return; } else { if (tjB > tiB) return; }
    const int i0 = tiB * 128, j0 = tjB * 128;

    const float* __restrict__ Ab;
    const float* __restrict__ Bb;
    float* __restrict__ Cb;
    size_t lda;
    int kbeg, kend;
    if (OP == 0) { Ab = g_proj[3] + b*SEQ*DHEAD; Bb = g_proj[2] + b*SEQ*DHEAD; Cb = g_term1[b]; lda = DHEAD; kbeg = 0; kend = DHEAD; }
    else if (OP == 1) { Ab = g_proj[3] + b*SEQ*DHEAD; Bb = g_proj[4] + b*SEQ*DHEAD; Cb = g_Sc[b]; lda = DHEAD; kbeg = 0; kend = DHEAD; }
    else if (OP == 2) { Ab = g_proj[0] + b*SEQ*DHEAD; Bb = g_proj[1] + b*SEQ*DHEAD; Cb = g_sig[b]; lda = DHEAD; kbeg = 0; kend = DHEAD; }
    else { Ab = g_term1[b]; Bb = g_sig[b]; Cb = g_Su[b]; lda = SEQ; kbeg = j0; kend = i0 + 128; }

    __shared__ uint32_t Ah[128][PITCH], Al[128][PITCH];
    __shared__ uint32_t Bh[128][PITCH], Bl[128][PITCH];

    const int tid = threadIdx.x;
    const int warp = tid >> 5, lane = tid & 31;
    const int g = lane >> 2, t = lane & 3;
    const int wm = (warp >> 1) * 64, wn = (warp & 1) * 64;
    float acc[4][8][4] = {};

    for (int kc = kbeg; kc < kend; kc += BK) {
        #pragma unroll
        for (int l = 0; l < 4; l++) {               // 128x16 float each for A and B
            int idx = tid + l * 128;
            int r = idx >> 2, c4 = (idx & 3) * 4;
            float4 av = *(const float4*)&Ab[(size_t)(i0 + r) * lda + kc + c4];
            split_store(&Ah[r][c4], &Al[r][c4], av);
            float4 bv = *(const float4*)&Bb[(size_t)(j0 + r) * lda + kc + c4];
            split_store(&Bh[r][c4], &Bl[r][c4], bv);
        }
        __syncthreads();
        #pragma unroll
        for (int ks = 0; ks < 2; ks++) {
            const int ko = ks * 8;
            uint32_t afh[4][4], afl[4][4];
            #pragma unroll
            for (int mt = 0; mt < 4; mt++) {
                int r0 = wm + mt * 16;
                afh[mt][0] = Ah[r0 + g][ko + t];     afh[mt][1] = Ah[r0 + g + 8][ko + t];
                afh[mt][2] = Ah[r0 + g][ko + t + 4]; afh[mt][3] = Ah[r0 + g + 8][ko + t + 4];
                afl[mt][0] = Al[r0 + g][ko + t];     afl[mt][1] = Al[r0 + g + 8][ko + t];
                afl[mt][2] = Al[r0 + g][ko + t + 4]; afl[mt][3] = Al[r0 + g + 8][ko + t + 4];
            }
            #pragma unroll
            for (int nt = 0; nt < 8; nt++) {
                int c0 = wn + nt * 8;
                uint32_t bh0 = Bh[c0 + g][ko + t], bh1 = Bh[c0 + g][ko + t + 4];
                uint32_t bl0 = Bl[c0 + g][ko + t], bl1 = Bl[c0 + g][ko + t + 4];
                #pragma unroll
                for (int mt = 0; mt < 4; mt++) {
                    mma_tf32(acc[mt][nt], afh[mt][0], afh[mt][1], afh[mt][2], afh[mt][3], bh0, bh1);
                    mma_tf32(acc[mt][nt], afh[mt][0], afh[mt][1], afh[mt][2], afh[mt][3], bl0, bl1);
                    mma_tf32(acc[mt][nt], afl[mt][0], afl[mt][1], afl[mt][2], afl[mt][3], bh0, bh1);
                }
            }
        }
        __syncthreads();
    }

    // Epilogue
    #pragma unroll
    for (int mt = 0; mt < 4; mt++) {
        const int gi0 = i0 + wm + mt * 16 + g;
        #pragma unroll
        for (int nt = 0; nt < 8; nt++) {
            const int gj = j0 + wn + nt * 8 + 2 * t;
            float v[4] = {acc[mt][nt][0], acc[mt][nt][1], acc[mt][nt][2], acc[mt][nt][3]};
            float o[4];
            #pragma unroll
            for (int e = 0; e < 4; e++) {
                const int gi = gi0 + (e >> 1) * 8;
                const int gjj = gj + (e & 1);
                if (OP == 0)      o[e] = (gjj <= gi) ? v[e] * SCALE : 0.0f;
                else if (OP == 1) o[e] = (gjj <= gi) ? v[e] * SCALE : -INFINITY;
                else if (OP == 2) o[e] = (gjj > gi) ? 1.0f / (1.0f + __expf(-v[e] * SCALE)) : 0.0f;
                else              o[e] = v[e];
            }
            *(float2*)&Cb[(size_t)gi0 * SEQ + gj]       = make_float2(o[0], o[1]);
            *(float2*)&Cb[(size_t)(gi0 + 8) * SEQ + gj] = make_float2(o[2], o[3]);
        }
    }
}

// ---------------------------------------------------------------------------
// Kernel 4: fused online softmax + attn @ V_c (unchanged from R6).
// One block per (b, 32-row i-tile), 256 threads: r=tid/8 (row), q=tid%8.
// ---------------------------------------------------------------------------
__global__ __launch_bounds__(256) void softmax_av_kernel(float* __restrict__ out) {
    const int t32 = blockIdx.x, b = blockIdx.y;
    __shared__ float Ls[32][65];
    __shared__ float Vs[64][64];
    const float* __restrict__ sc = g_Sc[b];
    const float* __restrict__ su = g_Su[b];
    const float* __restrict__ Vc = g_proj[5] + b * SEQ * DHEAD;
    const int tid = threadIdx.x;
    const int i0 = t32 * 32;
    const int r = tid >> 3, q = tid & 7, d0 = q * 8;
    const int njt = (t32 >> 1) + 1;     // 64-wide j tiles covering j<=i
    float m_prev = -INFINITY, Z = 0.0f;
    float acc[8] = {};
    for (int tj = 0; tj < njt; tj++) {
        const int j0 = tj * 64;
        __syncthreads();
        #pragma unroll
        for (int l = 0; l < 4; l++) {
            int idx = tid + l * 256;
            int rr = idx >> 4, cg = idx & 15;
            *(float4*)&Vs[rr][cg*4] = *(const float4*)&Vc[(j0 + rr) * DHEAD + cg * 4];
        }
        #pragma unroll
        for (int l = 0; l < 8; l++) {
            int idx = tid + l * 256;
            int rr = idx >> 6, cc = idx & 63;
            int gi = i0 + rr, gj = j0 + cc;
            float lv;
            if (gj > gi) {
                lv = -INFINITY;
            } else {
                float s = su[(size_t)gi * SEQ + gj];
                float sil = s / (1.0f + __expf(-s));
                lv = sc[(size_t)gi * SEQ + gj] - sil;
            }
            Ls[rr][cc] = lv;
        }
        __syncthreads();
        float mt = -INFINITY;
        #pragma unroll
        for (int c = 0; c < 8; c++) mt = fmaxf(mt, Ls[r][d0 + c]);
        mt = fmaxf(mt, __shfl_xor_sync(0xffffffffu, mt, 1));
        mt = fmaxf(mt, __shfl_xor_sync(0xffffffffu, mt, 2));
        mt = fmaxf(mt, __shfl_xor_sync(0xffffffffu, mt, 4));
        float m_new = fmaxf(m_prev, mt);
        float scl = __expf(m_prev - m_new);
        float zl = 0.0f;
        #pragma unroll
        for (int c = 0; c < 8; c++) {
            float p = __expf(Ls[r][d0 + c] - m_new);
            Ls[r][d0 + c] = p;
            zl += p;
        }
        zl += __shfl_xor_sync(0xffffffffu, zl, 1);
        zl += __shfl_xor_sync(0xffffffffu, zl, 2);
        zl += __shfl_xor_sync(0xffffffffu, zl, 4);
        Z = Z * scl + zl;
        m_prev = m_new;
        #pragma unroll
        for (int d = 0; d < 8; d++) acc[d] *= scl;
        __syncwarp();
        #pragma unroll 8
        for (int c = 0; c < 64; c++) {
            float p = Ls[r][c];
            float v[8];
            *(float4*)&v[0] = *(const float4*)&Vs[c][d0];
            *(float4*)&v[4] = *(const float4*)&Vs[c][d0 + 4];
            #pragma unroll
            for (int d = 0; d < 8; d++) acc[d] += p * v[d];
        }
    }
    const float inv = 1.0f / Z;
    const int gi = i0 + r;
    float* op = &out[((size_t)(b * SEQ + gi)) * DHEAD + d0];
    *(float4*)&op[0] = make_float4(acc[0]*inv, acc[1]*inv, acc[2]*inv, acc[3]*inv);
    *(float4*)&op[4] = make_float4(acc[4]*inv, acc[5]*inv, acc[6]*inv, acc[7]*inv);
}

// ---------------------------------------------------------------------------
extern "C" void kernel_launch(void* const* d_in, const int* in_sizes, int n_in,
                              void* d_out, int out_size) {
    const float* x = (const float*)d_in[0];
    WPtrs wp;
    for (int i = 0; i < 6; i++) wp.w[i] = (const float*)d_in[1 + i];

    dim3 g1((BATCH * SEQ) / 128, 6);
    proj_mma_kernel<<<g1, 128>>>(x, wp);

    dim3 g2(SEQ / 128, SEQ / 128, BATCH);
    mma_nt_kernel<0><<<g2, 128>>>();   // term1 = Qc.Vu^T (lower)
    mma_nt_kernel<1><<<g2, 128>>>();   // S_c   = Qc.Kc^T (lower)
    mma_nt_kernel<2><<<g2, 128>>>();   // sig   = sigmoid(Qu.Ku^T) (upper)
    mma_nt_kernel<3><<<g2, 128>>>();   // S_u   = term1 . sig^T (triangular K)

    dim3 g4(SEQ / 32, BATCH);
    softmax_av_kernel<<<g4, 256>>>((float*)d_out);
}